// round 13
// baseline (speedup 1.0000x reference)
#include <cuda_runtime.h>
#include <cstdint>

// Compact per-row maps (no clearing needed):
//   g_tok[d*T + rank] = global token id of the rank-th kept token in row d
//   g_total/g_zero: kept count, special zeroed slot (-1 if none)
#define MAX_D  64
#define MAX_DT (8 * 32768)
__device__ int g_tok[MAX_DT];
__device__ int g_total[MAX_D];
__device__ int g_zero[MAX_D];
__device__ volatile int g_ready[MAX_D];   // reset by setup itself each launch

__device__ __forceinline__ int mask_at(const void* mask, int mtype, long i) {
    if (mtype == 1) return ((const int*)mask)[i] != 0;          // int32
    if (mtype == 2) return ((const float*)mask)[i] != 0.0f;     // float32
    return ((const uint8_t*)mask)[i] != 0;                      // uint8/bool
}

// One block per cache row d (1024 threads). Resets its flag, fires the PDL
// trigger IMMEDIATELY (so the write kernel launches concurrently), then
// ballot-scans the mask row and publishes g_* + tail outputs, then sets the
// flag. Reset-before-trigger makes the flag handshake graph-replay-safe.
__global__ void setup_kernel(const void* __restrict__ mask,
                             const int* __restrict__ n_valid,
                             const int* __restrict__ index,
                             float* __restrict__ out_tail,
                             int D, int T, int M)
{
    const int d   = blockIdx.x;
    const int t   = threadIdx.x;
    const int NT  = blockDim.x;      // 1024
    const unsigned lane = t & 31u;
    const unsigned wid  = t >> 5;
    const int nw = NT >> 5;

    if (t == 0) g_ready[d] = 0;
    __syncthreads();
    __threadfence();
    cudaTriggerProgrammaticLaunchCompletion();

    // ---- mask dtype probe over this row's first T bytes ----
    // float32: 1.0f bytes 00 00 80 3f -> some byte > 1
    // int32  : nonzero bytes only at pos%4==0
    // uint8  : nonzero at pos%4!=0 (w.h.p.)
    __shared__ int s_gt1, s_nzmod, s_base;
    __shared__ int s_wcnt[32];
    if (t == 0) { s_gt1 = 0; s_nzmod = 0; s_base = 0; }
    __syncthreads();
    {
        const uint8_t* mb = (const uint8_t*)mask + (long)d * T;
        int gt1 = 0, nzmod = 0;
        for (int i = t; i < T; i += NT) {
            uint8_t b = mb[i];
            if (b > 1) gt1 = 1;
            else if (b != 0 && (i & 3)) nzmod = 1;
        }
        if (gt1)   atomicOr(&s_gt1, 1);
        if (nzmod) atomicOr(&s_nzmod, 1);
    }
    __syncthreads();
    const int mtype = s_gt1 ? 2 : (s_nzmod ? 0 : 1);
    const long mbase = (long)d * T;

    // ---- ballot-based rank scan, coalesced tiles of NT elements ----
    int* tok = g_tok + (long)d * T;
    for (int tile = 0; tile < T; tile += NT) {
        const int i = tile + t;
        const int b = (i < T) ? mask_at(mask, mtype, mbase + i) : 0;
        const unsigned bal = __ballot_sync(0xffffffffu, b);
        if (lane == 0) s_wcnt[wid] = __popc(bal);
        __syncthreads();
        int pre = 0;
        for (int w = 0; w < (int)wid; ++w) pre += s_wcnt[w];
        if (b) {
            const unsigned lt = (1u << lane) - 1u;
            tok[s_base + pre + __popc(bal & lt)] = d * T + i;
        }
        __syncthreads();
        if (t == 0) {
            int s = 0;
            for (int w = 0; w < nw; ++w) s += s_wcnt[w];
            s_base += s;
        }
        __syncthreads();
    }
    const int total = s_base;

    if (t == 0) {
        const int idx0 = index[d];
        g_total[d] = total;
        // First token masked -> offsets[0] = -1 -> slot (index-1) mod M is
        // set(0)+add(0) by the reference. Never collides with kept slots
        // (total < M).
        int zs = -1;
        if (T > 0 && !mask_at(mask, mtype, mbase) && total < M) {
            zs = idx0 - 1;
            if (zs < 0) zs += M;
        }
        g_zero[d] = zs;
        if (out_tail) {
            long nv = (long)n_valid[d] + total;
            if (nv > M) nv = M;
            out_tail[d]     = (float)nv;                     // new_n_valid
            out_tail[D + d] = (float)((idx0 + total) % M);   // new_index
        }
        __threadfence();             // publish g_* before the flag
        g_ready[d] = 1;
    }
}

// Grid (ceil(M/8), D). Block x covers ring RANKS T+8x .. T+8x+7 (mod M) of
// row d; slot = (idx0 + rank) mod M. Ranks in [T, M-2] are pure cache->out
// copies (total <= T always) and need nothing from setup; ranks wrapping into
// [0, T) or rank M-1 need g_* — those blocks have the HIGHEST x per d, so
// they are scheduled waves after setup's few-µs scan and the flag spin never
// engages. 8 back-to-back LDG.128 per thread (MLP_p1 = 8), streaming hints.
__global__ void write_kernel8(const float4* __restrict__ cache,
                              const float4* __restrict__ acts,
                              const int* __restrict__ index,
                              float4* __restrict__ out,
                              int DIM4, int M, int T)
{
    const int t  = threadIdx.x;
    const int d  = blockIdx.y;
    const int k0 = blockIdx.x * 8;          // rank = T + k0 + i  (pre-mod)
    const int idx0 = index[d];              // raw input: no setup dependency
    const long rowd = (long)d * M;
    const int rk = T + k0;

    if (k0 + 7 < M && rk + 7 <= M - 2) {
        // Fast path: ranks in [T, M-2] -> always old cache value.
        long r[8];
        #pragma unroll
        for (int i = 0; i < 8; ++i) {
            int s = idx0 + rk + i;          // <= 2M-3: one subtract suffices
            if (s >= M) s -= M;
            r[i] = rowd + s;
        }
        float4 v[8];
        #pragma unroll
        for (int i = 0; i < 8; ++i) v[i] = __ldcs(cache + r[i] * DIM4 + t);
        #pragma unroll
        for (int i = 0; i < 8; ++i) __stcs(out + r[i] * DIM4 + t, v[i]);
        return;
    }

    // Slow path: ranks may wrap into [0, T) (acts source) or hit M-1 (the
    // possibly-zeroed slot). Scheduled ~waves after setup finished.
    if (t == 0) { while (g_ready[d] == 0) __nanosleep(128); }
    __syncthreads();
    __threadfence();                        // order g_* reads after flag

    const int total = g_total[d];
    const int zslot = g_zero[d];
    const int* tok  = g_tok + (long)d * T;

    const int n = (k0 + 8 <= M) ? 8 : (M - k0);
    for (int i = 0; i < n; ++i) {
        int rank = rk + i; if (rank >= M) rank -= M;
        int s = idx0 + rank; if (s >= M) s -= M;
        const long r = rowd + s;
        const bool fa = rank < total;
        const int  tk = fa ? tok[rank] : 0;
        const float4* p = (fa ? acts + (long)tk * DIM4 : cache + r * DIM4) + t;
        float4 v = __ldcs(p);
        if (s == zslot) v = make_float4(0.f, 0.f, 0.f, 0.f);
        __stcs(out + r * DIM4 + t, v);
    }
}

extern "C" void kernel_launch(void* const* d_in, const int* in_sizes, int n_in,
                              void* d_out, int out_size)
{
    const float* cache   = (const float*)d_in[0];
    const float* acts    = (const float*)d_in[1];
    const void*  mask    = (const void*)d_in[2];
    const int*   n_valid = (const int*)d_in[3];
    const int*   index   = (const int*)d_in[4];

    const int  D      = in_sizes[3];                      // 8
    const long DT     = (long)in_sizes[2];                // D*T
    const int  T      = (int)(DT / D);                    // 4096
    const int  DIM    = (int)((long)in_sizes[1] / DT);    // 768
    const long cacheN = (long)in_sizes[0];                // D*M*DIM
    const int  M      = (int)(cacheN / ((long)D * DIM));  // 32768
    const int  DIM4   = DIM / 4;                          // 192

    float* out  = (float*)d_out;
    float* tail = ((long)out_size >= cacheN + 2L * D) ? (out + cacheN) : nullptr;

    setup_kernel<<<D, 1024>>>(mask, n_valid, index, tail, D, T, M);

    // PDL: setup fires its trigger first thing, so this launches (and its
    // fast-path blocks run) concurrently with setup's scan. Slow blocks are
    // rank-ordered to the end of each row's block range and spin on the
    // per-row flag only if setup were somehow still running.
    {
        const float4* c4 = (const float4*)cache;
        const float4* a4 = (const float4*)acts;
        float4*       o4 = (float4*)out;

        cudaLaunchConfig_t cfg = {};
        cfg.gridDim  = dim3((unsigned)((M + 7) / 8), (unsigned)D, 1);
        cfg.blockDim = dim3((unsigned)DIM4, 1, 1);
        cfg.dynamicSmemBytes = 0;
        cfg.stream = 0;

        cudaLaunchAttribute attr[1];
        attr[0].id = cudaLaunchAttributeProgrammaticStreamSerialization;
        attr[0].val.programmaticStreamSerializationAllowed = 1;
        cfg.attrs = attr;
        cfg.numAttrs = 1;

        cudaLaunchKernelEx(&cfg, write_kernel8, c4, a4, index, o4, DIM4, M, T);
    }
}

// round 14
// speedup vs baseline: 1.0064x; 1.0064x over previous
#include <cuda_runtime.h>
#include <cstdint>

// Compact per-row maps (no clearing needed):
//   g_tok[d*T + rank] = global token id of the rank-th kept token in row d
//   g_total/g_zero: kept count, special zeroed slot (-1 if none)
#define MAX_D  64
#define MAX_DT (8 * 32768)
__device__ int g_tok[MAX_DT];
__device__ int g_total[MAX_D];
__device__ int g_zero[MAX_D];
__device__ volatile int g_ready[MAX_D];   // reset by setup itself each launch

__device__ __forceinline__ int mask_at(const void* mask, int mtype, long i) {
    if (mtype == 1) return ((const int*)mask)[i] != 0;          // int32
    if (mtype == 2) return ((const float*)mask)[i] != 0.0f;     // float32
    return ((const uint8_t*)mask)[i] != 0;                      // uint8/bool
}

// One block per cache row d (1024 threads). Resets its flag, fires the PDL
// trigger IMMEDIATELY (so the write kernel launches concurrently), then
// ballot-scans the mask row and publishes g_* + tail outputs, then sets the
// flag. Reset-before-trigger makes the flag handshake graph-replay-safe.
__global__ void setup_kernel(const void* __restrict__ mask,
                             const int* __restrict__ n_valid,
                             const int* __restrict__ index,
                             float* __restrict__ out_tail,
                             int D, int T, int M)
{
    const int d   = blockIdx.x;
    const int t   = threadIdx.x;
    const int NT  = blockDim.x;      // 1024
    const unsigned lane = t & 31u;
    const unsigned wid  = t >> 5;
    const int nw = NT >> 5;

    if (t == 0) g_ready[d] = 0;
    __syncthreads();
    __threadfence();
    cudaTriggerProgrammaticLaunchCompletion();

    // ---- mask dtype probe over this row's first T bytes ----
    // float32: 1.0f bytes 00 00 80 3f -> some byte > 1
    // int32  : nonzero bytes only at pos%4==0
    // uint8  : nonzero at pos%4!=0 (w.h.p.)
    __shared__ int s_gt1, s_nzmod, s_base;
    __shared__ int s_wcnt[32];
    if (t == 0) { s_gt1 = 0; s_nzmod = 0; s_base = 0; }
    __syncthreads();
    {
        const uint8_t* mb = (const uint8_t*)mask + (long)d * T;
        int gt1 = 0, nzmod = 0;
        for (int i = t; i < T; i += NT) {
            uint8_t b = mb[i];
            if (b > 1) gt1 = 1;
            else if (b != 0 && (i & 3)) nzmod = 1;
        }
        if (gt1)   atomicOr(&s_gt1, 1);
        if (nzmod) atomicOr(&s_nzmod, 1);
    }
    __syncthreads();
    const int mtype = s_gt1 ? 2 : (s_nzmod ? 0 : 1);
    const long mbase = (long)d * T;

    // ---- ballot-based rank scan, coalesced tiles of NT elements ----
    int* tok = g_tok + (long)d * T;
    for (int tile = 0; tile < T; tile += NT) {
        const int i = tile + t;
        const int b = (i < T) ? mask_at(mask, mtype, mbase + i) : 0;
        const unsigned bal = __ballot_sync(0xffffffffu, b);
        if (lane == 0) s_wcnt[wid] = __popc(bal);
        __syncthreads();
        int pre = 0;
        for (int w = 0; w < (int)wid; ++w) pre += s_wcnt[w];
        if (b) {
            const unsigned lt = (1u << lane) - 1u;
            tok[s_base + pre + __popc(bal & lt)] = d * T + i;
        }
        __syncthreads();
        if (t == 0) {
            int s = 0;
            for (int w = 0; w < nw; ++w) s += s_wcnt[w];
            s_base += s;
        }
        __syncthreads();
    }
    const int total = s_base;

    if (t == 0) {
        const int idx0 = index[d];
        g_total[d] = total;
        // First token masked -> offsets[0] = -1 -> slot (index-1) mod M is
        // set(0)+add(0) by the reference. Never collides with kept slots
        // (total < M).
        int zs = -1;
        if (T > 0 && !mask_at(mask, mtype, mbase) && total < M) {
            zs = idx0 - 1;
            if (zs < 0) zs += M;
        }
        g_zero[d] = zs;
        if (out_tail) {
            long nv = (long)n_valid[d] + total;
            if (nv > M) nv = M;
            out_tail[d]     = (float)nv;                     // new_n_valid
            out_tail[D + d] = (float)((idx0 + total) % M);   // new_index
        }
        __threadfence();             // publish g_* before the flag
        g_ready[d] = 1;
    }
}

// Slow write path: waits on the per-row flag, then resolves acts/cache/zero
// per slot. __noinline__ quarantines its register demand away from the
// fast-path copy loop.
__device__ __noinline__ void write_slow(const float4* __restrict__ cache,
                                        const float4* __restrict__ acts,
                                        float4* __restrict__ out,
                                        int d, int idx0, int s0, int n,
                                        int T, int M, int DIM4, long rowd)
{
    const int t = threadIdx.x;

    if (t == 0) { while (g_ready[d] == 0) __nanosleep(64); }
    __syncthreads();
    __threadfence();                        // order g_* reads after flag

    const int total = g_total[d];
    const int zslot = g_zero[d];
    const int* tok  = g_tok + (long)d * T;

    for (int i = 0; i < n; ++i) {
        const int s = s0 + i;
        int rank = s - idx0; if (rank < 0) rank += M;
        const long r = rowd + s;
        const bool fa = rank < total;
        const int  tk = fa ? tok[rank] : 0;
        const float4* p = (fa ? acts + (long)tk * DIM4 : cache + r * DIM4) + t;
        float4 v = __ldcs(p);
        if (s == zslot) v = make_float4(0.f, 0.f, 0.f, 0.f);
        __stcs(out + r * DIM4 + t, v);
    }
}

// Grid (ceil(M/8), D). A block covers slots 8x..8x+7 of row d (slot-direct:
// the proven 85.9-86.3%-of-peak access pattern). idx0 comes from the raw
// `index` input, so only blocks whose rank window can touch acts (rank < T)
// or the zeroed slot (rank == M-1) take the slow path — setup finishes within
// a few µs while ~87% of blocks stream immediately. 8 back-to-back LDG.128
// per thread (MLP_p1 = 8), streaming hints (every byte touched once).
__global__ void __launch_bounds__(192, 8)
write_kernel8(const float4* __restrict__ cache,
              const float4* __restrict__ acts,
              const int* __restrict__ index,
              float4* __restrict__ out,
              int DIM4, int M, int T)
{
    const int t  = threadIdx.x;
    const int d  = blockIdx.y;
    const int s0 = blockIdx.x * 8;
    const int idx0 = index[d];              // raw input: no setup dependency
    const long rowd = (long)d * M;

    int rank0 = s0 - idx0;
    if (rank0 < 0) rank0 += M;
    // Ranks covered by this block: rank0..rank0+7 (mod M).
    const bool fast = (s0 + 7 < M) && !((rank0 < T) || (rank0 >= M - 8));

    if (fast) {
        // Pure cache -> out copy; independent of setup results.
        const long base = (rowd + s0) * DIM4 + t;
        float4 v[8];
        #pragma unroll
        for (int i = 0; i < 8; ++i) v[i] = __ldcs(cache + base + (long)i * DIM4);
        #pragma unroll
        for (int i = 0; i < 8; ++i) __stcs(out + base + (long)i * DIM4, v[i]);
    } else {
        const int n = (s0 + 8 <= M) ? 8 : (M - s0);
        write_slow(cache, acts, out, d, idx0, s0, n, T, M, DIM4, rowd);
    }
}

extern "C" void kernel_launch(void* const* d_in, const int* in_sizes, int n_in,
                              void* d_out, int out_size)
{
    const float* cache   = (const float*)d_in[0];
    const float* acts    = (const float*)d_in[1];
    const void*  mask    = (const void*)d_in[2];
    const int*   n_valid = (const int*)d_in[3];
    const int*   index   = (const int*)d_in[4];

    const int  D      = in_sizes[3];                      // 8
    const long DT     = (long)in_sizes[2];                // D*T
    const int  T      = (int)(DT / D);                    // 4096
    const int  DIM    = (int)((long)in_sizes[1] / DT);    // 768
    const long cacheN = (long)in_sizes[0];                // D*M*DIM
    const int  M      = (int)(cacheN / ((long)D * DIM));  // 32768
    const int  DIM4   = DIM / 4;                          // 192

    float* out  = (float*)d_out;
    float* tail = ((long)out_size >= cacheN + 2L * D) ? (out + cacheN) : nullptr;

    setup_kernel<<<D, 1024>>>(mask, n_valid, index, tail, D, T, M);

    // PDL: setup fires its trigger first thing, so this launches (and its
    // fast-path blocks run) concurrently with setup's scan. Slow blocks spin
    // on the per-row flag, which setup reset before triggering.
    {
        const float4* c4 = (const float4*)cache;
        const float4* a4 = (const float4*)acts;
        float4*       o4 = (float4*)out;

        cudaLaunchConfig_t cfg = {};
        cfg.gridDim  = dim3((unsigned)((M + 7) / 8), (unsigned)D, 1);
        cfg.blockDim = dim3((unsigned)DIM4, 1, 1);
        cfg.dynamicSmemBytes = 0;
        cfg.stream = 0;

        cudaLaunchAttribute attr[1];
        attr[0].id = cudaLaunchAttributeProgrammaticStreamSerialization;
        attr[0].val.programmaticStreamSerializationAllowed = 1;
        cfg.attrs = attr;
        cfg.numAttrs = 1;

        cudaLaunchKernelEx(&cfg, write_kernel8, c4, a4, index, o4, DIM4, M, T);
    }
}

// round 15
// speedup vs baseline: 1.0168x; 1.0104x over previous
#include <cuda_runtime.h>
#include <cstdint>

// Compact per-row maps (no clearing needed):
//   g_tok[d*T + rank] = global token id of the rank-th kept token in row d
//   g_total/g_zero: kept count, special zeroed slot (-1 if none)
#define MAX_D  64
#define MAX_DT (8 * 32768)
__device__ int g_tok[MAX_DT];
__device__ int g_total[MAX_D];
__device__ int g_zero[MAX_D];
__device__ volatile int g_ready[MAX_D];   // reset by setup itself each launch

__device__ __forceinline__ int mask_at(const void* mask, int mtype, long i) {
    if (mtype == 1) return ((const int*)mask)[i] != 0;          // int32
    if (mtype == 2) return ((const float*)mask)[i] != 0.0f;     // float32
    return ((const uint8_t*)mask)[i] != 0;                      // uint8/bool
}

// One block per cache row d (1024 threads). Resets its flag, fires the PDL
// trigger IMMEDIATELY (so the write kernel launches concurrently), then
// ballot-scans the mask row and publishes g_* + tail outputs, then sets the
// flag. Reset-before-trigger makes the flag handshake graph-replay-safe.
__global__ void setup_kernel(const void* __restrict__ mask,
                             const int* __restrict__ n_valid,
                             const int* __restrict__ index,
                             float* __restrict__ out_tail,
                             int D, int T, int M)
{
    const int d   = blockIdx.x;
    const int t   = threadIdx.x;
    const int NT  = blockDim.x;      // 1024
    const unsigned lane = t & 31u;
    const unsigned wid  = t >> 5;
    const int nw = NT >> 5;

    // Reset flag, then allow the dependent launch: every write block observes
    // g_ready[d]==0 until this launch's scan completes.
    if (t == 0) g_ready[d] = 0;
    __syncthreads();
    __threadfence();
    cudaTriggerProgrammaticLaunchCompletion();

    // ---- mask dtype probe over this row's first T bytes ----
    // float32: 1.0f bytes 00 00 80 3f -> some byte > 1
    // int32  : nonzero bytes only at pos%4==0
    // uint8  : nonzero at pos%4!=0 (w.h.p.)
    __shared__ int s_gt1, s_nzmod, s_base;
    __shared__ int s_wcnt[32];
    if (t == 0) { s_gt1 = 0; s_nzmod = 0; s_base = 0; }
    __syncthreads();
    {
        const uint8_t* mb = (const uint8_t*)mask + (long)d * T;
        int gt1 = 0, nzmod = 0;
        for (int i = t; i < T; i += NT) {
            uint8_t b = mb[i];
            if (b > 1) gt1 = 1;
            else if (b != 0 && (i & 3)) nzmod = 1;
        }
        if (gt1)   atomicOr(&s_gt1, 1);
        if (nzmod) atomicOr(&s_nzmod, 1);
    }
    __syncthreads();
    const int mtype = s_gt1 ? 2 : (s_nzmod ? 0 : 1);
    const long mbase = (long)d * T;

    // ---- ballot-based rank scan, coalesced tiles of NT elements ----
    int* tok = g_tok + (long)d * T;
    for (int tile = 0; tile < T; tile += NT) {
        const int i = tile + t;
        const int b = (i < T) ? mask_at(mask, mtype, mbase + i) : 0;
        const unsigned bal = __ballot_sync(0xffffffffu, b);
        if (lane == 0) s_wcnt[wid] = __popc(bal);
        __syncthreads();
        int pre = 0;
        for (int w = 0; w < (int)wid; ++w) pre += s_wcnt[w];
        if (b) {
            const unsigned lt = (1u << lane) - 1u;
            tok[s_base + pre + __popc(bal & lt)] = d * T + i;
        }
        __syncthreads();
        if (t == 0) {
            int s = 0;
            for (int w = 0; w < nw; ++w) s += s_wcnt[w];
            s_base += s;
        }
        __syncthreads();
    }
    const int total = s_base;

    if (t == 0) {
        const int idx0 = index[d];
        g_total[d] = total;
        // First token masked -> offsets[0] = -1 -> slot (index-1) mod M is
        // set(0)+add(0) by the reference. Never collides with kept slots
        // (total < M).
        int zs = -1;
        if (T > 0 && !mask_at(mask, mtype, mbase) && total < M) {
            zs = idx0 - 1;
            if (zs < 0) zs += M;
        }
        g_zero[d] = zs;
        if (out_tail) {
            long nv = (long)n_valid[d] + total;
            if (nv > M) nv = M;
            out_tail[d]     = (float)nv;                     // new_n_valid
            out_tail[D + d] = (float)((idx0 + total) % M);   // new_index
        }
        __threadfence();             // publish g_* before the flag
        g_ready[d] = 1;
    }
}

// Grid (ceil(M/8), D). A block covers slots 8x..8x+7 of row d (slot-direct:
// the proven 86%-of-peak access pattern). idx0 comes from the raw `index`
// input, so only blocks whose rank window can touch acts (rank < T) or the
// zeroed slot (rank == M-1) spin on g_ready[d] — setup finishes within a few
// µs while 87% of blocks stream immediately. 8 back-to-back LDG.128 per
// thread (MLP_p1 = 8), streaming hints (every byte touched once).
__global__ void write_kernel8(const float4* __restrict__ cache,
                              const float4* __restrict__ acts,
                              const int* __restrict__ index,
                              float4* __restrict__ out,
                              int DIM4, int M, int T)
{
    const int t  = threadIdx.x;
    const int d  = blockIdx.y;
    const int s0 = blockIdx.x * 8;

    if (s0 + 7 < M) {
        const int idx0 = index[d];           // raw input: no setup dependency
        int rank0 = s0 - idx0;
        if (rank0 < 0) rank0 += M;
        // Ranks covered by this block: rank0..rank0+7 (mod M).
        const bool needs_sync = (rank0 < T) || (rank0 >= M - 8);

        const long rowb = (long)d * M + s0;

        if (!needs_sync) {
            // Pure cache -> out copy; independent of setup results.
            const float4* c = cache + rowb * DIM4 + t;
            float4 v[8];
            #pragma unroll
            for (int i = 0; i < 8; ++i) v[i] = __ldcs(c + (long)i * DIM4);
            float4* o = out + rowb * DIM4 + t;
            #pragma unroll
            for (int i = 0; i < 8; ++i) __stcs(o + (long)i * DIM4, v[i]);
            return;
        }

        if (t == 0) { while (g_ready[d] == 0) __nanosleep(64); }
        __syncthreads();
        __threadfence();                     // order g_* reads after flag

        const int total = g_total[d];
        const int zslot = g_zero[d];
        const int* tok  = g_tok + (long)d * T;

        const float4* p[8];
        int zo[8];
        #pragma unroll
        for (int i = 0; i < 8; ++i) {
            const int s = s0 + i;
            int rank = s - idx0;
            if (rank < 0) rank += M;
            const bool fa = rank < total;
            const int  tk = fa ? tok[rank] : 0;
            p[i] = (fa ? acts + (long)tk * DIM4
                       : cache + (rowb + i) * DIM4) + t;
            zo[i] = (s == zslot);
        }

        float4 v[8];
        #pragma unroll
        for (int i = 0; i < 8; ++i) v[i] = __ldcs(p[i]);

        const float4 z = make_float4(0.f, 0.f, 0.f, 0.f);
        float4* o = out + rowb * DIM4 + t;
        #pragma unroll
        for (int i = 0; i < 8; ++i) {
            if (zo[i]) v[i] = z;
            __stcs(o + (long)i * DIM4, v[i]);
        }
    } else {
        // Tail (M not divisible by 8): always sync, scalar path.
        if (t == 0) { while (g_ready[d] == 0) __nanosleep(64); }
        __syncthreads();
        __threadfence();
        const int idx0  = index[d];
        const int total = g_total[d];
        const int zslot = g_zero[d];
        const int* tok  = g_tok + (long)d * T;
        for (int i = 0; s0 + i < M; ++i) {
            const int s = s0 + i;
            int rank = s - idx0;
            if (rank < 0) rank += M;
            const bool fa = rank < total;
            const int  tk = fa ? tok[rank] : 0;
            const long r = (long)d * M + s;
            const float4* p = (fa ? acts + (long)tk * DIM4
                                  : cache + r * DIM4) + t;
            float4 v = __ldcs(p);
            if (s == zslot) v = make_float4(0.f, 0.f, 0.f, 0.f);
            __stcs(out + r * DIM4 + t, v);
        }
    }
}

extern "C" void kernel_launch(void* const* d_in, const int* in_sizes, int n_in,
                              void* d_out, int out_size)
{
    const float* cache   = (const float*)d_in[0];
    const float* acts    = (const float*)d_in[1];
    const void*  mask    = (const void*)d_in[2];
    const int*   n_valid = (const int*)d_in[3];
    const int*   index   = (const int*)d_in[4];

    const int  D      = in_sizes[3];                      // 8
    const long DT     = (long)in_sizes[2];                // D*T
    const int  T      = (int)(DT / D);                    // 4096
    const int  DIM    = (int)((long)in_sizes[1] / DT);    // 768
    const long cacheN = (long)in_sizes[0];                // D*M*DIM
    const int  M      = (int)(cacheN / ((long)D * DIM));  // 32768
    const int  DIM4   = DIM / 4;                          // 192

    float* out  = (float*)d_out;
    float* tail = ((long)out_size >= cacheN + 2L * D) ? (out + cacheN) : nullptr;

    setup_kernel<<<D, 1024>>>(mask, n_valid, index, tail, D, T, M);

    // PDL: setup fires its trigger at the start, so this launches (and its
    // fast-path blocks run) concurrently with setup's scan. Slow blocks spin
    // on the per-row flag, which setup reset before triggering.
    {
        const float4* c4 = (const float4*)cache;
        const float4* a4 = (const float4*)acts;
        float4*       o4 = (float4*)out;

        cudaLaunchConfig_t cfg = {};
        cfg.gridDim  = dim3((unsigned)((M + 7) / 8), (unsigned)D, 1);
        cfg.blockDim = dim3((unsigned)DIM4, 1, 1);
        cfg.dynamicSmemBytes = 0;
        cfg.stream = 0;

        cudaLaunchAttribute attr[1];
        attr[0].id = cudaLaunchAttributeProgrammaticStreamSerialization;
        attr[0].val.programmaticStreamSerializationAllowed = 1;
        cfg.attrs = attr;
        cfg.numAttrs = 1;

        cudaLaunchKernelEx(&cfg, write_kernel8, c4, a4, index, o4, DIM4, M, T);
    }
}